// round 9
// baseline (speedup 1.0000x reference)
#include <cuda_runtime.h>
#include <stdint.h>

// MessagePassing: out[dst[e]] += x[src[e]], N=100000, E=1600000, D=32 fp32.
// edge_index int32 [2, E]: row 0 = src, row 1 = dst.
//
// Partition pipeline (removes the 205MB RED atomic L2 traffic):
//   B) partition edges by dst>>8 into global buckets; 1 packed 4B word/edge
//      (src<<8 | dst&255). Overflow -> global overflow list.
//   C) 1 CTA per partition: coalesced bucket read, smem counting-sort by
//      node, node-major register accumulation (8 lanes/node, MLP=4, tree
//      adds), one plain 128B store per node (so no out memset needed).
//   D) rare overflow edges applied via red.global.add.v4.f32 after C.

#define D_FEAT     32
#define CHUNKS     8          // D_FEAT / 4
#define PART_BITS  8
#define PART_SIZE  256        // nodes per partition
#define MAX_NODES  131072
#define MAX_PARTS  (MAX_NODES / PART_SIZE)   // 512
#define BUCKET_CAP 4608       // mean 4092 (Poisson), +8 sigma headroom
#define OVF_CAP    (1u << 21) // 2M edges: covers worst case for E <= 2M

__device__ unsigned g_cursor[MAX_PARTS];
__device__ unsigned g_ovf_cnt;
__device__ unsigned g_buckets[(long)MAX_PARTS * BUCKET_CAP];  // 9.4 MB
__device__ int2     g_ovf[OVF_CAP];                           // 16 MB

__device__ __forceinline__ void red_add_v4(float* p, float4 v) {
    asm volatile("red.global.add.v4.f32 [%0], {%1, %2, %3, %4};"
                 :: "l"(p), "f"(v.x), "f"(v.y), "f"(v.z), "f"(v.w)
                 : "memory");
}

__device__ __forceinline__ float4 f4add(float4 a, float4 b) {
    return make_float4(a.x + b.x, a.y + b.y, a.z + b.z, a.w + b.w);
}

// ---------------- Phase B: partition edges ----------------
__device__ __forceinline__ void part_one(int s, int d) {
    unsigned part = (unsigned)d >> PART_BITS;
    unsigned pos  = atomicAdd(&g_cursor[part], 1u);
    if (pos < BUCKET_CAP) {
        g_buckets[(long)part * BUCKET_CAP + pos] =
            ((unsigned)s << PART_BITS) | ((unsigned)d & (PART_SIZE - 1));
    } else {
        unsigned o = atomicAdd(&g_ovf_cnt, 1u);
        if (o < OVF_CAP) g_ovf[o] = make_int2(s, d);
        // o >= OVF_CAP impossible: host guards n_edges <= OVF_CAP.
    }
}

__global__ void mp_part_kernel(const int* __restrict__ src,
                               const int* __restrict__ dst,
                               long n_edges) {
    long t  = (long)blockIdx.x * blockDim.x + threadIdx.x;
    long e0 = t * 8;
    if (e0 >= n_edges) return;
    if (e0 + 8 <= n_edges) {
        int4 sa = __ldg((const int4*)(src + e0));
        int4 sb = __ldg((const int4*)(src + e0 + 4));
        int4 da = __ldg((const int4*)(dst + e0));
        int4 db = __ldg((const int4*)(dst + e0 + 4));
        part_one(sa.x, da.x); part_one(sa.y, da.y);
        part_one(sa.z, da.z); part_one(sa.w, da.w);
        part_one(sb.x, db.x); part_one(sb.y, db.y);
        part_one(sb.z, db.z); part_one(sb.w, db.w);
    } else {
        for (long e = e0; e < n_edges; ++e)
            part_one(__ldg(&src[e]), __ldg(&dst[e]));
    }
}

// ---------------- Phase C: per-partition sort + accumulate ----------------
__global__ void __launch_bounds__(PART_SIZE)
mp_agg_kernel(const float4* __restrict__ x,
              float4* __restrict__ out,
              int n_nodes) {
    __shared__ unsigned s_words[BUCKET_CAP];
    __shared__ unsigned s_sorted[BUCKET_CAP];
    __shared__ unsigned s_hist[PART_SIZE];
    __shared__ unsigned s_scan[PART_SIZE];
    __shared__ unsigned s_cur[PART_SIZE];

    int p   = blockIdx.x;
    int tid = threadIdx.x;

    s_hist[tid] = 0;
    __syncthreads();

    unsigned raw = g_cursor[p];
    int cnt = raw < BUCKET_CAP ? (int)raw : BUCKET_CAP;
    const unsigned* bucket = g_buckets + (long)p * BUCKET_CAP;

    // Coalesced bucket load + histogram by local node id.
    for (int i = tid; i < cnt; i += PART_SIZE) {
        unsigned w = __ldg(&bucket[i]);
        s_words[i] = w;
        atomicAdd(&s_hist[w & (PART_SIZE - 1)], 1u);
    }
    __syncthreads();

    // Inclusive Hillis-Steele scan of s_hist -> s_scan.
    unsigned v = s_hist[tid];
    s_scan[tid] = v;
    __syncthreads();
    #pragma unroll
    for (int dshift = 1; dshift < PART_SIZE; dshift <<= 1) {
        unsigned add = (tid >= dshift) ? s_scan[tid - dshift] : 0u;
        __syncthreads();
        s_scan[tid] += add;
        __syncthreads();
    }
    s_cur[tid] = s_scan[tid] - v;   // exclusive offset
    __syncthreads();

    // Counting-sort scatter (smem only).
    for (int i = tid; i < cnt; i += PART_SIZE) {
        unsigned w = s_words[i];
        unsigned pos = atomicAdd(&s_cur[w & (PART_SIZE - 1)], 1u);
        s_sorted[pos] = w;
    }
    __syncthreads();

    // Node-major accumulate: 32 groups x 8 lanes; lane c owns chunk c.
    int grp = tid >> 3;
    int c   = tid & 7;
    for (int nl = grp; nl < PART_SIZE; nl += 32) {
        int n = (p << PART_BITS) + nl;
        if (n >= n_nodes) break;   // nl monotone; only last partition trims
        int k  = (int)s_hist[nl];
        int lo = (int)(s_scan[nl]) - k;   // inclusive end - count = start
        float4 acc = make_float4(0.f, 0.f, 0.f, 0.f);
        int j = lo, end = lo + k;
        for (; j + 4 <= end; j += 4) {
            unsigned w0 = s_sorted[j], w1 = s_sorted[j + 1];
            unsigned w2 = s_sorted[j + 2], w3 = s_sorted[j + 3];
            float4 a0 = __ldg(&x[(long)(w0 >> PART_BITS) * CHUNKS + c]);
            float4 a1 = __ldg(&x[(long)(w1 >> PART_BITS) * CHUNKS + c]);
            float4 a2 = __ldg(&x[(long)(w2 >> PART_BITS) * CHUNKS + c]);
            float4 a3 = __ldg(&x[(long)(w3 >> PART_BITS) * CHUNKS + c]);
            acc = f4add(acc, f4add(f4add(a0, a1), f4add(a2, a3)));
        }
        for (; j < end; ++j) {
            unsigned w = s_sorted[j];
            acc = f4add(acc, __ldg(&x[(long)(w >> PART_BITS) * CHUNKS + c]));
        }
        out[(long)n * CHUNKS + c] = acc;   // plain store: no memset needed
    }
}

// ---------------- Phase D: rare overflow edges ----------------
__global__ void mp_ovf_kernel(const float4* __restrict__ x,
                              float* __restrict__ out) {
    unsigned cnt = g_ovf_cnt;
    if (cnt > OVF_CAP) cnt = OVF_CAP;
    for (unsigned i = blockIdx.x * blockDim.x + threadIdx.x; i < cnt;
         i += gridDim.x * blockDim.x) {
        int2 e = g_ovf[i];
        #pragma unroll
        for (int c = 0; c < CHUNKS; ++c)
            red_add_v4(out + (long)e.y * D_FEAT + c * 4,
                       __ldg(&x[(long)e.x * CHUNKS + c]));
    }
}

// ---------------- Fallback: edge-centric RED (R8) ----------------
__global__ void mp_scatter_kernel(const float4* __restrict__ x,
                                  const int* __restrict__ src,
                                  const int* __restrict__ dst,
                                  float* __restrict__ out,
                                  long n_edges) {
    long t = (long)blockIdx.x * blockDim.x + threadIdx.x;
    long e = t >> 3;
    int  c = (int)(t & 7);
    if (e >= n_edges) return;
    int s = __ldg(&src[e]);
    int d = __ldg(&dst[e]);
    float4 v = __ldg(&x[(long)s * CHUNKS + c]);
    red_add_v4(out + (long)d * D_FEAT + c * 4, v);
}

extern "C" void kernel_launch(void* const* d_in, const int* in_sizes, int n_in,
                              void* d_out, int out_size) {
    const float4* x   = (const float4*)d_in[0];
    const int*    ei  = (const int*)d_in[1];
    long n_edges = (long)in_sizes[1] / 2;
    const int* src = ei;
    const int* dst = ei + n_edges;
    float* out = (float*)d_out;
    int n_nodes = in_sizes[0] / D_FEAT;
    int threads = 256;

    if (n_nodes > MAX_NODES || n_edges > (long)OVF_CAP) {
        // Shape-safety fallback: edge-centric RED path.
        cudaMemsetAsync(d_out, 0, (size_t)out_size * sizeof(float), 0);
        long total = n_edges * CHUNKS;
        long blocks = (total + threads - 1) / threads;
        mp_scatter_kernel<<<(unsigned)blocks, threads>>>(x, src, dst, out, n_edges);
        return;
    }

    // Zero cursors + overflow count (re-zeroed every replay).
    void* cur_ptr = nullptr; cudaGetSymbolAddress(&cur_ptr, g_cursor);
    void* ovf_ptr = nullptr; cudaGetSymbolAddress(&ovf_ptr, g_ovf_cnt);
    cudaMemsetAsync(cur_ptr, 0, sizeof(unsigned) * MAX_PARTS, 0);
    cudaMemsetAsync(ovf_ptr, 0, sizeof(unsigned), 0);

    // Phase B: partition (8 edges/thread).
    {
        long groups = (n_edges + 7) / 8;
        long blocks = (groups + threads - 1) / threads;
        mp_part_kernel<<<(unsigned)blocks, threads>>>(src, dst, n_edges);
    }
    // Phase C: one CTA per partition.
    {
        int parts = (n_nodes + PART_SIZE - 1) / PART_SIZE;
        mp_agg_kernel<<<parts, PART_SIZE>>>(x, (float4*)out, n_nodes);
    }
    // Phase D: overflow (normally empty).
    mp_ovf_kernel<<<32, 256>>>(x, out);
}

// round 10
// speedup vs baseline: 6.1414x; 6.1414x over previous
#include <cuda_runtime.h>
#include <stdint.h>

// MessagePassing: out[dst[e]] += x[src[e]], N=100000, E=1600000, D=32 fp32.
// edge_index int32 [2, E]: row 0 = src, row 1 = dst.
//
// Partition pipeline v2:
//   B) CTA-aggregated multi-split: smem histogram of dst>>8 per 8192-edge
//      tile, ONE global cursor atomicAdd per (CTA, partition) (fixes R9's
//      391-address atomic serialization), then scattered packed-word writes
//      (src<<8 | dst&255) into reserved bucket slots.
//   C) 1 CTA per partition: coalesced bucket read, smem counting-sort by
//      node, node-major register accumulation (8 lanes/node, MLP=8, tree
//      adds), one plain 128B store per node (no out memset needed).
//   D) rare bucket-overflow edges applied via RED after C.

#define D_FEAT     32
#define CHUNKS     8
#define PART_BITS  8
#define PART_SIZE  256
#define MAX_NODES  131072
#define MAX_PARTS  (MAX_NODES / PART_SIZE)   // 512
#define BUCKET_CAP 4608       // Poisson mean 4092 + ~8 sigma
#define OVF_CAP    (1u << 21) // host guards n_edges <= 2M

#define B_THREADS  512
#define B_EPT      16
#define B_TILE     (B_THREADS * B_EPT)       // 8192 edges per CTA

__device__ unsigned g_cursor[MAX_PARTS];
__device__ unsigned g_ovf_cnt;
__device__ unsigned g_buckets[(long)MAX_PARTS * BUCKET_CAP];
__device__ int2     g_ovf[OVF_CAP];

__device__ __forceinline__ void red_add_v4(float* p, float4 v) {
    asm volatile("red.global.add.v4.f32 [%0], {%1, %2, %3, %4};"
                 :: "l"(p), "f"(v.x), "f"(v.y), "f"(v.z), "f"(v.w)
                 : "memory");
}

__device__ __forceinline__ float4 f4add(float4 a, float4 b) {
    return make_float4(a.x + b.x, a.y + b.y, a.z + b.z, a.w + b.w);
}

// ---------------- Phase B: CTA-aggregated multi-split ----------------
__global__ void __launch_bounds__(B_THREADS)
mp_part_kernel(const int* __restrict__ src,
               const int* __restrict__ dst,
               long n_edges) {
    __shared__ unsigned s_hist[MAX_PARTS];
    __shared__ unsigned s_gbase[MAX_PARTS];
    __shared__ unsigned s_cur[MAX_PARTS];

    int tid = threadIdx.x;
    long base = (long)blockIdx.x * B_TILE;
    long e_lo = base + (long)tid * B_EPT;

    s_hist[tid] = 0;               // B_THREADS == MAX_PARTS == 512
    __syncthreads();

    // Pass 1: histogram partitions (smem atomics, spread addresses).
    for (int j = 0; j < B_EPT; j += 4) {
        long e = e_lo + j;
        if (e + 4 <= n_edges) {
            int4 d4 = __ldg((const int4*)(dst + e));
            atomicAdd(&s_hist[(unsigned)d4.x >> PART_BITS], 1u);
            atomicAdd(&s_hist[(unsigned)d4.y >> PART_BITS], 1u);
            atomicAdd(&s_hist[(unsigned)d4.z >> PART_BITS], 1u);
            atomicAdd(&s_hist[(unsigned)d4.w >> PART_BITS], 1u);
        } else {
            for (; e < n_edges; ++e)
                atomicAdd(&s_hist[(unsigned)__ldg(&dst[e]) >> PART_BITS], 1u);
            break;
        }
    }
    __syncthreads();

    // Bulk reservation: one global atomic per non-empty (CTA, partition).
    unsigned cnt = s_hist[tid];
    s_cur[tid] = 0;
    if (cnt) s_gbase[tid] = atomicAdd(&g_cursor[tid], cnt);
    __syncthreads();

    // Pass 2: re-read indices (L1/L2-hot) and write packed words.
    for (int j = 0; j < B_EPT; j += 4) {
        long e = e_lo + j;
        if (e + 4 <= n_edges) {
            int4 s4 = __ldg((const int4*)(src + e));
            int4 d4 = __ldg((const int4*)(dst + e));
            int ss[4] = {s4.x, s4.y, s4.z, s4.w};
            int dd[4] = {d4.x, d4.y, d4.z, d4.w};
            #pragma unroll
            for (int q = 0; q < 4; ++q) {
                unsigned p = (unsigned)dd[q] >> PART_BITS;
                unsigned w = ((unsigned)ss[q] << PART_BITS) |
                             ((unsigned)dd[q] & (PART_SIZE - 1));
                unsigned loc  = atomicAdd(&s_cur[p], 1u);
                unsigned gpos = s_gbase[p] + loc;
                if (gpos < BUCKET_CAP) {
                    g_buckets[(long)p * BUCKET_CAP + gpos] = w;
                } else {
                    unsigned o = atomicAdd(&g_ovf_cnt, 1u);
                    if (o < OVF_CAP) g_ovf[o] = make_int2(ss[q], dd[q]);
                }
            }
        } else {
            for (; e < n_edges; ++e) {
                int s = __ldg(&src[e]);
                int d = __ldg(&dst[e]);
                unsigned p = (unsigned)d >> PART_BITS;
                unsigned w = ((unsigned)s << PART_BITS) |
                             ((unsigned)d & (PART_SIZE - 1));
                unsigned loc  = atomicAdd(&s_cur[p], 1u);
                unsigned gpos = s_gbase[p] + loc;
                if (gpos < BUCKET_CAP) {
                    g_buckets[(long)p * BUCKET_CAP + gpos] = w;
                } else {
                    unsigned o = atomicAdd(&g_ovf_cnt, 1u);
                    if (o < OVF_CAP) g_ovf[o] = make_int2(s, d);
                }
            }
            break;
        }
    }
}

// ---------------- Phase C: per-partition sort + accumulate ----------------
__global__ void __launch_bounds__(PART_SIZE)
mp_agg_kernel(const float4* __restrict__ x,
              float4* __restrict__ out,
              int n_nodes) {
    __shared__ unsigned s_words[BUCKET_CAP];
    __shared__ unsigned s_sorted[BUCKET_CAP];
    __shared__ unsigned s_hist[PART_SIZE];
    __shared__ unsigned s_scan[PART_SIZE];
    __shared__ unsigned s_cur[PART_SIZE];

    int p   = blockIdx.x;
    int tid = threadIdx.x;

    s_hist[tid] = 0;
    __syncthreads();

    unsigned raw = g_cursor[p];
    int cnt = raw < BUCKET_CAP ? (int)raw : BUCKET_CAP;
    const unsigned* bucket = g_buckets + (long)p * BUCKET_CAP;

    for (int i = tid; i < cnt; i += PART_SIZE) {
        unsigned w = __ldg(&bucket[i]);
        s_words[i] = w;
        atomicAdd(&s_hist[w & (PART_SIZE - 1)], 1u);
    }
    __syncthreads();

    // Inclusive Hillis-Steele scan.
    unsigned v = s_hist[tid];
    s_scan[tid] = v;
    __syncthreads();
    #pragma unroll
    for (int dshift = 1; dshift < PART_SIZE; dshift <<= 1) {
        unsigned add = (tid >= dshift) ? s_scan[tid - dshift] : 0u;
        __syncthreads();
        s_scan[tid] += add;
        __syncthreads();
    }
    s_cur[tid] = s_scan[tid] - v;
    __syncthreads();

    // Counting-sort scatter (smem only).
    for (int i = tid; i < cnt; i += PART_SIZE) {
        unsigned w = s_words[i];
        unsigned pos = atomicAdd(&s_cur[w & (PART_SIZE - 1)], 1u);
        s_sorted[pos] = w;
    }
    __syncthreads();

    // Node-major accumulate: 32 groups x 8 lanes; lane c owns chunk c.
    int grp = tid >> 3;
    int c   = tid & 7;
    for (int nl = grp; nl < PART_SIZE; nl += 32) {
        int n = (p << PART_BITS) + nl;
        if (n >= n_nodes) break;
        int k  = (int)s_hist[nl];
        int lo = (int)s_scan[nl] - k;
        float4 acc = make_float4(0.f, 0.f, 0.f, 0.f);
        int j = lo, end = lo + k;
        for (; j + 8 <= end; j += 8) {
            float4 a0 = __ldg(&x[(long)(s_sorted[j    ] >> PART_BITS) * CHUNKS + c]);
            float4 a1 = __ldg(&x[(long)(s_sorted[j + 1] >> PART_BITS) * CHUNKS + c]);
            float4 a2 = __ldg(&x[(long)(s_sorted[j + 2] >> PART_BITS) * CHUNKS + c]);
            float4 a3 = __ldg(&x[(long)(s_sorted[j + 3] >> PART_BITS) * CHUNKS + c]);
            float4 a4 = __ldg(&x[(long)(s_sorted[j + 4] >> PART_BITS) * CHUNKS + c]);
            float4 a5 = __ldg(&x[(long)(s_sorted[j + 5] >> PART_BITS) * CHUNKS + c]);
            float4 a6 = __ldg(&x[(long)(s_sorted[j + 6] >> PART_BITS) * CHUNKS + c]);
            float4 a7 = __ldg(&x[(long)(s_sorted[j + 7] >> PART_BITS) * CHUNKS + c]);
            float4 s03 = f4add(f4add(a0, a1), f4add(a2, a3));
            float4 s47 = f4add(f4add(a4, a5), f4add(a6, a7));
            acc = f4add(acc, f4add(s03, s47));
        }
        if (j + 4 <= end) {
            float4 a0 = __ldg(&x[(long)(s_sorted[j    ] >> PART_BITS) * CHUNKS + c]);
            float4 a1 = __ldg(&x[(long)(s_sorted[j + 1] >> PART_BITS) * CHUNKS + c]);
            float4 a2 = __ldg(&x[(long)(s_sorted[j + 2] >> PART_BITS) * CHUNKS + c]);
            float4 a3 = __ldg(&x[(long)(s_sorted[j + 3] >> PART_BITS) * CHUNKS + c]);
            acc = f4add(acc, f4add(f4add(a0, a1), f4add(a2, a3)));
            j += 4;
        }
        for (; j < end; ++j)
            acc = f4add(acc, __ldg(&x[(long)(s_sorted[j] >> PART_BITS) * CHUNKS + c]));
        out[(long)n * CHUNKS + c] = acc;
    }
}

// ---------------- Phase D: rare overflow edges ----------------
__global__ void mp_ovf_kernel(const float4* __restrict__ x,
                              float* __restrict__ out) {
    unsigned cnt = g_ovf_cnt;
    if (cnt > OVF_CAP) cnt = OVF_CAP;
    for (unsigned i = blockIdx.x * blockDim.x + threadIdx.x; i < cnt;
         i += gridDim.x * blockDim.x) {
        int2 e = g_ovf[i];
        #pragma unroll
        for (int c = 0; c < CHUNKS; ++c)
            red_add_v4(out + (long)e.y * D_FEAT + c * 4,
                       __ldg(&x[(long)e.x * CHUNKS + c]));
    }
}

// ---------------- Fallback: edge-centric RED (R8) ----------------
__global__ void mp_scatter_kernel(const float4* __restrict__ x,
                                  const int* __restrict__ src,
                                  const int* __restrict__ dst,
                                  float* __restrict__ out,
                                  long n_edges) {
    long t = (long)blockIdx.x * blockDim.x + threadIdx.x;
    long e = t >> 3;
    int  c = (int)(t & 7);
    if (e >= n_edges) return;
    int s = __ldg(&src[e]);
    int d = __ldg(&dst[e]);
    float4 v = __ldg(&x[(long)s * CHUNKS + c]);
    red_add_v4(out + (long)d * D_FEAT + c * 4, v);
}

extern "C" void kernel_launch(void* const* d_in, const int* in_sizes, int n_in,
                              void* d_out, int out_size) {
    const float4* x   = (const float4*)d_in[0];
    const int*    ei  = (const int*)d_in[1];
    long n_edges = (long)in_sizes[1] / 2;
    const int* src = ei;
    const int* dst = ei + n_edges;
    float* out = (float*)d_out;
    int n_nodes = in_sizes[0] / D_FEAT;
    int threads = 256;

    if (n_nodes > MAX_NODES || n_edges > (long)OVF_CAP) {
        cudaMemsetAsync(d_out, 0, (size_t)out_size * sizeof(float), 0);
        long total = n_edges * CHUNKS;
        long blocks = (total + threads - 1) / threads;
        mp_scatter_kernel<<<(unsigned)blocks, threads>>>(x, src, dst, out, n_edges);
        return;
    }

    void* cur_ptr = nullptr; cudaGetSymbolAddress(&cur_ptr, g_cursor);
    void* ovf_ptr = nullptr; cudaGetSymbolAddress(&ovf_ptr, g_ovf_cnt);
    cudaMemsetAsync(cur_ptr, 0, sizeof(unsigned) * MAX_PARTS, 0);
    cudaMemsetAsync(ovf_ptr, 0, sizeof(unsigned), 0);

    // Phase B: CTA-aggregated multi-split.
    {
        long blocks = (n_edges + B_TILE - 1) / B_TILE;
        mp_part_kernel<<<(unsigned)blocks, B_THREADS>>>(src, dst, n_edges);
    }
    // Phase C: one CTA per partition.
    {
        int parts = (n_nodes + PART_SIZE - 1) / PART_SIZE;
        mp_agg_kernel<<<parts, PART_SIZE>>>(x, (float4*)out, n_nodes);
    }
    // Phase D: overflow (normally empty).
    mp_ovf_kernel<<<32, 256>>>(x, out);
}